// round 1
// baseline (speedup 1.0000x reference)
#include <cuda_runtime.h>
#include <math.h>

#define SEQN 2048
#define NAMP 256

// ---- device scratch (no allocations allowed) ----
__device__ float g_trig[2 * 63];      // cos,sin of w[j]/2
__device__ float g_q[SEQN];           // QCNN outputs <Z_7> per sample
__device__ float g_hs[SEQN * 4];      // LSTM hidden states

// ============================================================
// Kernel 1: precompute cos/sin of ansatz half-angles (once)
// ============================================================
__global__ void prep_kernel(const float* __restrict__ w) {
    int j = threadIdx.x;
    if (j < 63) {
        float s, c;
        sincosf(0.5f * w[j], &s, &c);
        g_trig[2 * j]     = c;
        g_trig[2 * j + 1] = s;
    }
}

// ============================================================
// Kernel 2: QCNN — one block (256 threads) per sample,
// thread tid owns amplitude index tid of the 8-qubit state.
// Diagonal gates (RZ, P) are local; H/RY/CNOT exchange via
// ping-pong shared buffers with ONE __syncthreads per gate.
// ============================================================
__global__ void qcnn_kernel(const float* __restrict__ sentence) {
    __shared__ float2 buf[2][NAMP];
    __shared__ float tc[63], ts[63];
    __shared__ float xc[8], xs[8];
    __shared__ float red[8];

    const int tid = threadIdx.x;
    const int s   = blockIdx.x;

    if (tid < 63) { tc[tid] = g_trig[2 * tid]; ts[tid] = g_trig[2 * tid + 1]; }
    if (tid >= 64 && tid < 72) {
        int q = tid - 64;
        float x = sentence[s * 8 + q];
        float sn, cs;
        sincosf(2.0f * x, &sn, &cs);
        xc[q] = cs; xs[q] = sn;
    }
    __syncthreads();

    float re = (tid == 0) ? 1.0f : 0.0f;
    float im = 0.0f;
    int pb = 0;
    const float RT = 0.70710678118654752440f;

    auto H = [&](int q) {
        buf[pb][tid] = make_float2(re, im);
        __syncthreads();
        float2 o = buf[pb][tid ^ (1 << q)];
        pb ^= 1;
        if ((tid >> q) & 1) { re = (o.x - re) * RT; im = (o.y - im) * RT; }
        else                { re = (re + o.x) * RT; im = (im + o.y) * RT; }
    };
    auto PH = [&](int q, float c, float sn) {   // diag(1, e^{it})
        if ((tid >> q) & 1) {
            float nr = re * c - im * sn;
            im = re * sn + im * c;
            re = nr;
        }
    };
    auto RZ = [&](int q, float c, float sn) {   // diag(e^{-it/2}, e^{it/2}); (c,sn)=cos,sin(t/2)
        float ss = ((tid >> q) & 1) ? sn : -sn;
        float nr = re * c - im * ss;
        im = re * ss + im * c;
        re = nr;
    };
    auto RY = [&](int q, float c, float sn) {   // (c,sn)=cos,sin(t/2)
        buf[pb][tid] = make_float2(re, im);
        __syncthreads();
        float2 o = buf[pb][tid ^ (1 << q)];
        pb ^= 1;
        float ss = ((tid >> q) & 1) ? sn : -sn;
        re = c * re + ss * o.x;
        im = c * im + ss * o.y;
    };
    auto CNOT = [&](int cq, int tq) {
        buf[pb][tid] = make_float2(re, im);
        __syncthreads();
        int src = ((tid >> cq) & 1) ? (tid ^ (1 << tq)) : tid;
        float2 o = buf[pb][src];
        pb ^= 1;
        re = o.x; im = o.y;
    };
    auto conv = [&](int a, int b, int k) {
        RZ(b, RT, -RT);                 // RZ(-pi/2)
        CNOT(b, a);
        RZ(a, tc[k], ts[k]);
        RY(b, tc[k + 1], ts[k + 1]);
        CNOT(a, b);
        RY(b, tc[k + 2], ts[k + 2]);
        CNOT(b, a);
        RZ(a, RT, RT);                  // RZ(+pi/2)
    };
    auto pool = [&](int a, int b, int k) {
        RZ(b, RT, -RT);
        CNOT(b, a);
        RZ(a, tc[k], ts[k]);
        RY(b, tc[k + 1], ts[k + 1]);
        CNOT(a, b);
        RY(b, tc[k + 2], ts[k + 2]);
    };

    // ZFeatureMap: H then P(2x_q)
#pragma unroll
    for (int q = 0; q < 8; q++) { H(q); PH(q, xc[q], xs[q]); }

    int k = 0;
    // CONV1
    conv(0, 1, k); k += 3;  conv(2, 3, k); k += 3;
    conv(4, 5, k); k += 3;  conv(6, 7, k); k += 3;
    conv(1, 2, k); k += 3;  conv(3, 4, k); k += 3;
    conv(5, 6, k); k += 3;  conv(7, 0, k); k += 3;
    // POOL1
    pool(0, 4, k); k += 3;  pool(1, 5, k); k += 3;
    pool(2, 6, k); k += 3;  pool(3, 7, k); k += 3;
    // CONV2
    conv(0, 1, k); k += 3;  conv(2, 3, k); k += 3;
    conv(1, 2, k); k += 3;  conv(3, 0, k); k += 3;
    // POOL2
    pool(0, 2, k); k += 3;  pool(1, 3, k); k += 3;
    // CONV3
    conv(0, 1, k); k += 3;  conv(1, 0, k); k += 3;
    // POOL3
    pool(0, 1, k); k += 3;

    // <Z_7>: sign by bit 7
    float p = re * re + im * im;
    float v = (tid & 128) ? -p : p;
#pragma unroll
    for (int o = 16; o; o >>= 1) v += __shfl_xor_sync(0xFFFFFFFFu, v, o);
    if ((tid & 31) == 0) red[tid >> 5] = v;
    __syncthreads();
    if (tid == 0) {
        float sv = 0.0f;
#pragma unroll
        for (int i = 0; i < 8; i++) sv += red[i];
        g_q[s] = sv;
    }
}

// ============================================================
// Kernel 3: QLSTM sequential scan. One block; 16 active lanes
// (lane = gate*4 + q). The 4-qubit quantum layer is collapsed
// analytically to cosine products (CNOT ring = GF(2) permutation):
//   z0=c1c2c3, z1=c0c1, z2=c0c1c2, z3=c0c1c2c3
// ============================================================
__global__ void qlstm_kernel(const float* __restrict__ Wf, const float* __restrict__ bf,
                             const float* __restrict__ Wi, const float* __restrict__ bi,
                             const float* __restrict__ Wu, const float* __restrict__ bu,
                             const float* __restrict__ Wo, const float* __restrict__ bo,
                             const float* __restrict__ thf, const float* __restrict__ thi,
                             const float* __restrict__ thu, const float* __restrict__ tho) {
    __shared__ float sq[SEQN];
    const int tid = threadIdx.x;
    for (int i = tid; i < SEQN; i += blockDim.x) sq[i] = g_q[i];
    __syncthreads();
    if (tid >= 16) return;

    const int g = tid >> 2;
    const int q = tid & 3;

    const float* W  = (g == 0) ? Wf  : (g == 1) ? Wi  : (g == 2) ? Wu  : Wo;
    const float* b  = (g == 0) ? bf  : (g == 1) ? bi  : (g == 2) ? bu  : bo;
    const float* th = (g == 0) ? thf : (g == 1) ? thi : (g == 2) ? thu : tho;

    const float W0 = W[q * 5 + 0];
    const float w1 = W[q * 5 + 1], w2 = W[q * 5 + 2];
    const float w3 = W[q * 5 + 3], w4 = W[q * 5 + 4];
    const float ub = b[q] + th[q];

    const bool use0 = (q != 0);
    const bool use2 = (q != 1);
    const bool use3 = (q == 0) || (q == 3);
    // gate u (g==2) uses tanh: tanh(z) = 2*sigmoid(2z) - 1
    const float zs = (g == 2) ? -2.0f : -1.0f;
    const float aA = (g == 2) ?  2.0f :  1.0f;
    const float aB = (g == 2) ? -1.0f :  0.0f;

    float c = 0.0f, h0 = 0.0f, h1 = 0.0f, h2 = 0.0f, h3 = 0.0f;
    const unsigned M = 0x0000FFFFu;
    const int base = tid & ~3;

    for (int t = 0; t < SEQN; t++) {
        float y = fmaf(W0, sq[t], ub);
        y = fmaf(w1, h0, y);
        y = fmaf(w2, h1, y);
        y = fmaf(w3, h2, y);
        y = fmaf(w4, h3, y);
        float cz = __cosf(y);

        float c0 = __shfl_sync(M, cz, base + 0);
        float c1 = __shfl_sync(M, cz, base + 1);
        float c2 = __shfl_sync(M, cz, base + 2);
        float c3 = __shfl_sync(M, cz, base + 3);

        float z = c1;
        if (use0) z *= c0;
        if (use2) z *= c2;
        if (use3) z *= c3;

        float r   = __fdividef(1.0f, 1.0f + __expf(zs * z));
        float act = fmaf(aA, r, aB);

        float af = __shfl_sync(M, act, q);
        float ai = __shfl_sync(M, act, 4 + q);
        float au = __shfl_sync(M, act, 8 + q);
        float ao = __shfl_sync(M, act, 12 + q);

        c = fmaf(af, c, ai * au);
        float tch = fmaf(2.0f, __fdividef(1.0f, 1.0f + __expf(-2.0f * c)), -1.0f);
        float hq = ao * tch;

        if (g == 0) g_hs[t * 4 + q] = hq;

        h0 = __shfl_sync(M, hq, base + 0);
        h1 = __shfl_sync(M, hq, base + 1);
        h2 = __shfl_sync(M, hq, base + 2);
        h3 = __shfl_sync(M, hq, base + 3);
    }
}

// ============================================================
// Kernel 4: logits + log_softmax. One warp per timestep row,
// lane = tag (TAGS = 32).
// ============================================================
__global__ void head_kernel(const float* __restrict__ Wt, const float* __restrict__ bt,
                            float* __restrict__ out) {
    const int warp = (blockIdx.x * blockDim.x + threadIdx.x) >> 5;
    const int lane = threadIdx.x & 31;
    if (warp >= SEQN) return;

    float h0 = g_hs[warp * 4 + 0];
    float h1 = g_hs[warp * 4 + 1];
    float h2 = g_hs[warp * 4 + 2];
    float h3 = g_hs[warp * 4 + 3];

    float l = bt[lane];
    l = fmaf(h0, Wt[lane * 4 + 0], l);
    l = fmaf(h1, Wt[lane * 4 + 1], l);
    l = fmaf(h2, Wt[lane * 4 + 2], l);
    l = fmaf(h3, Wt[lane * 4 + 3], l);

    float m = l;
#pragma unroll
    for (int o = 16; o; o >>= 1) m = fmaxf(m, __shfl_xor_sync(0xFFFFFFFFu, m, o));
    float e = __expf(l - m);
    float sum = e;
#pragma unroll
    for (int o = 16; o; o >>= 1) sum += __shfl_xor_sync(0xFFFFFFFFu, sum, o);

    out[warp * 32 + lane] = (l - m) - __logf(sum);
}

// ============================================================
extern "C" void kernel_launch(void* const* d_in, const int* in_sizes, int n_in,
                              void* d_out, int out_size) {
    const float* sentence = (const float*)d_in[0];
    const float* qcnn_w   = (const float*)d_in[1];
    const float* Wf  = (const float*)d_in[2];
    const float* bf  = (const float*)d_in[3];
    const float* Wi  = (const float*)d_in[4];
    const float* bi  = (const float*)d_in[5];
    const float* Wu  = (const float*)d_in[6];
    const float* bu  = (const float*)d_in[7];
    const float* Wo  = (const float*)d_in[8];
    const float* bo  = (const float*)d_in[9];
    const float* thf = (const float*)d_in[10];
    const float* thi = (const float*)d_in[11];
    const float* thu = (const float*)d_in[12];
    const float* tho = (const float*)d_in[13];
    const float* Wt  = (const float*)d_in[14];
    const float* bt  = (const float*)d_in[15];
    float* out = (float*)d_out;

    prep_kernel<<<1, 64>>>(qcnn_w);
    qcnn_kernel<<<SEQN, NAMP>>>(sentence);
    qlstm_kernel<<<1, 256>>>(Wf, bf, Wi, bi, Wu, bu, Wo, bo, thf, thi, thu, tho);
    head_kernel<<<(SEQN * 32) / 256, 256>>>(Wt, bt, out);
}